// round 11
// baseline (speedup 1.0000x reference)
#include <cuda_runtime.h>
#include <cstdint>

#define BATCH 4
#define NPTS  4096
#define DIM   128
#define TM    128          // desc1 rows per CTA
#define TN    64           // desc2 rows per col-tile
#define NTILES (NPTS / TN) // 64
#define SSTR  132          // smem row stride in floats (DIM + 4 pad)
#define RATIO 0.85f
#define EPSV  1e-8f

// Scratch (allocation-free rule: __device__ globals)
__device__ float g_v1[BATCH * NPTS];
__device__ float g_v2[BATCH * NPTS];
__device__ int   g_i1[BATCH * NPTS];

// dynamic smem layout in floats
#define A_HI 0
#define A_LO (TM * SSTR)
#define B_HI (2 * TM * SSTR)
#define B_LO (2 * TM * SSTR + TN * SSTR)
#define SM_FLOATS (2 * TM * SSTR + 2 * TN * SSTR)   // 50688 floats = 202752 B

__device__ __forceinline__ uint32_t f2tf32(float x) {
    uint32_t r;
    asm("cvt.rna.tf32.f32 %0, %1;" : "=r"(r) : "f"(x));
    return r;
}

__device__ __forceinline__ void mma_tf32(float* c, const uint32_t* a, uint32_t b0, uint32_t b1) {
    asm volatile(
        "mma.sync.aligned.m16n8k8.row.col.f32.tf32.tf32.f32 "
        "{%0,%1,%2,%3}, {%4,%5,%6,%7}, {%8,%9}, {%0,%1,%2,%3};"
        : "+f"(c[0]), "+f"(c[1]), "+f"(c[2]), "+f"(c[3])
        : "r"(a[0]), "r"(a[1]), "r"(a[2]), "r"(a[3]), "r"(b0), "r"(b1));
}

// Split 8 logical k-values (two float4) into tf32 hi/lo and store k-interleaved:
// physical order l0,l4,l1,l5,l2,l6,l3,l7 so fragment pairs (k, k+4) are 8B-adjacent.
__device__ __forceinline__ void split8_store(float* hi_p, float* lo_p, float4 v0, float4 v1) {
    float p0 = v0.x, p1 = v1.x, p2 = v0.y, p3 = v1.y;
    float p4 = v0.z, p5 = v1.z, p6 = v0.w, p7 = v1.w;
    uint4 h0, h1, l0, l1;
    h0.x = f2tf32(p0); h0.y = f2tf32(p1); h0.z = f2tf32(p2); h0.w = f2tf32(p3);
    h1.x = f2tf32(p4); h1.y = f2tf32(p5); h1.z = f2tf32(p6); h1.w = f2tf32(p7);
    l0.x = f2tf32(p0 - __uint_as_float(h0.x));
    l0.y = f2tf32(p1 - __uint_as_float(h0.y));
    l0.z = f2tf32(p2 - __uint_as_float(h0.z));
    l0.w = f2tf32(p3 - __uint_as_float(h0.w));
    l1.x = f2tf32(p4 - __uint_as_float(h1.x));
    l1.y = f2tf32(p5 - __uint_as_float(h1.y));
    l1.z = f2tf32(p6 - __uint_as_float(h1.z));
    l1.w = f2tf32(p7 - __uint_as_float(h1.w));
    *(uint4*)hi_p       = h0;
    *(uint4*)(hi_p + 4) = h1;
    *(uint4*)lo_p       = l0;
    *(uint4*)(lo_p + 4) = l1;
}

// ---------------------------------------------------------------------------
// Kernel 1: 3xTF32 mma.sync GEMM (sim = D1 * D2^T) with fused per-row top-2.
// 256 threads = 8 warps (4 m x 2 n), warp tile 32x32. LDS.64 fragment loads
// via k-interleaved smem; register-prefetched B tiles.
// ---------------------------------------------------------------------------
__global__ __launch_bounds__(256, 1) void sim_top2_mma(const float* __restrict__ d1,
                                                       const float* __restrict__ d2) {
    extern __shared__ float sm[];

    const int tid  = threadIdx.x;
    const int wid  = tid >> 5;
    const int lane = tid & 31;
    const int g    = lane >> 2;     // fragment row group
    const int tig  = lane & 3;      // thread in group
    const int wm   = wid & 3;       // warp m-group: rows wm*32..+31
    const int wn   = wid >> 2;      // warp n-group: cols wn*32..+31

    const int b    = blockIdx.y;
    const int row0 = blockIdx.x * TM;

    // ---- load + split A tile [TM x DIM], k-interleaved (once) ----
    {
        const float4* A = (const float4*)(d1 + (size_t)b * NPTS * DIM);
#pragma unroll
        for (int c = 0; c < 8; c++) {
            int i   = tid + 256 * c;          // chunk id: TM*DIM/8 = 2048 chunks
            int row = i >> 4, k8 = i & 15;
            float4 v0 = A[(size_t)(row0 + row) * 32 + 2 * k8];
            float4 v1 = A[(size_t)(row0 + row) * 32 + 2 * k8 + 1];
            split8_store(sm + A_HI + row * SSTR + k8 * 8,
                         sm + A_LO + row * SSTR + k8 * 8, v0, v1);
        }
    }

    // warp-local smem bases
    const float* As_hi = sm + A_HI + (wm * 32) * SSTR;
    const float* As_lo = sm + A_LO + (wm * 32) * SSTR;
    const float* Bs_hi = sm + B_HI + (wn * 32) * SSTR;
    const float* Bs_lo = sm + B_LO + (wn * 32) * SSTR;

    float t1[4], t2[4];
    int   i1[4];
#pragma unroll
    for (int s = 0; s < 4; s++) { t1[s] = -1e30f; t2[s] = -1e30f; i1[s] = 0; }

    const float4* Bm = (const float4*)(d2 + (size_t)b * NPTS * DIM);

    // prefetch tile 0 into registers (4 chunks x 2 float4 per thread)
    float4 pre[8];
#pragma unroll
    for (int c = 0; c < 4; c++) {
        int i   = tid + 256 * c;              // TN*DIM/8 = 1024 chunks
        int row = i >> 4, k8 = i & 15;
        pre[2 * c]     = Bm[(size_t)row * 32 + 2 * k8];
        pre[2 * c + 1] = Bm[(size_t)row * 32 + 2 * k8 + 1];
    }

    for (int t = 0; t < NTILES; t++) {
        const int c0 = t * TN;

        __syncthreads();  // tile t-1 readers done (t=0: covers A stores too)
#pragma unroll
        for (int c = 0; c < 4; c++) {
            int i   = tid + 256 * c;
            int row = i >> 4, k8 = i & 15;
            split8_store(sm + B_HI + row * SSTR + k8 * 8,
                         sm + B_LO + row * SSTR + k8 * 8, pre[2 * c], pre[2 * c + 1]);
        }
        __syncthreads();

        // prefetch tile t+1 (hidden behind the HMMA loop below)
        if (t + 1 < NTILES) {
            const float4* Bn = Bm + (size_t)(c0 + TN) * 32;
#pragma unroll
            for (int c = 0; c < 4; c++) {
                int i   = tid + 256 * c;
                int row = i >> 4, k8 = i & 15;
                pre[2 * c]     = Bn[(size_t)row * 32 + 2 * k8];
                pre[2 * c + 1] = Bn[(size_t)row * 32 + 2 * k8 + 1];
            }
        }

        float acc[2][4][4];
#pragma unroll
        for (int mt = 0; mt < 2; mt++)
#pragma unroll
            for (int nt = 0; nt < 4; nt++)
#pragma unroll
                for (int c = 0; c < 4; c++) acc[mt][nt][c] = 0.f;

#pragma unroll 8
        for (int ks = 0; ks < 16; ks++) {
            const int kb = ks * 8 + 2 * tig;

            // B fragments: one LDS.64 -> (b0, b1) = (k0+tig, k0+tig+4)
            uint2 bh[4], bl[4];
#pragma unroll
            for (int nt = 0; nt < 4; nt++) {
                int off = (nt * 8 + g) * SSTR + kb;
                bh[nt] = *(const uint2*)(Bs_hi + off);
                bl[nt] = *(const uint2*)(Bs_lo + off);
            }

#pragma unroll
            for (int mt = 0; mt < 2; mt++) {
                int off = (mt * 16 + g) * SSTR + kb;
                uint2 a02h = *(const uint2*)(As_hi + off);
                uint2 a13h = *(const uint2*)(As_hi + off + 8 * SSTR);
                uint2 a02l = *(const uint2*)(As_lo + off);
                uint2 a13l = *(const uint2*)(As_lo + off + 8 * SSTR);
                uint32_t ah[4] = {a02h.x, a13h.x, a02h.y, a13h.y};
                uint32_t al[4] = {a02l.x, a13l.x, a02l.y, a13l.y};
#pragma unroll
                for (int nt = 0; nt < 4; nt++) {
                    mma_tf32(acc[mt][nt], ah, bh[nt].x, bh[nt].y);  // hi*hi
                    mma_tf32(acc[mt][nt], ah, bl[nt].x, bl[nt].y);  // hi*lo
                    mma_tf32(acc[mt][nt], al, bh[nt].x, bh[nt].y);  // lo*hi
                }
            }
        }

        // Fused running top-2: slot s = mt*2 + h owns row (mt*16 + h*8 + g).
        // Columns ascend -> strict '>' keeps lowest index on ties (top_k semantics).
#pragma unroll
        for (int mt = 0; mt < 2; mt++) {
#pragma unroll
            for (int h = 0; h < 2; h++) {
                const int s = mt * 2 + h;
#pragma unroll
                for (int nt = 0; nt < 4; nt++) {
#pragma unroll
                    for (int j = 0; j < 2; j++) {
                        float v = acc[mt][nt][h * 2 + j];
                        int   c = c0 + wn * 32 + nt * 8 + 2 * tig + j;
                        if (v > t1[s])      { t2[s] = t1[s]; t1[s] = v; i1[s] = c; }
                        else if (v > t2[s]) { t2[s] = v; }
                    }
                }
            }
        }
    }

    // ---- final merge: 8 partials per row (2 warp_n x 4 tig), reuse smem ----
    __syncthreads();
    float* mv1 = sm;                  // [128][8]
    float* mv2 = sm + 1024;
    int*   mi1 = (int*)(sm + 2048);

#pragma unroll
    for (int s = 0; s < 4; s++) {
        int r = wm * 32 + s * 8 + g;
        int e = wn * 4 + tig;
        mv1[r * 8 + e] = t1[s];
        mv2[r * 8 + e] = t2[s];
        mi1[r * 8 + e] = i1[s];
    }
    __syncthreads();

    if (tid < TM) {
        float V1 = -1e30f, V2 = -1e30f;
        int   I1 = 0;
#pragma unroll
        for (int e = 0; e < 8; e++) {
            float v1c = mv1[tid * 8 + e];
            float v2c = mv2[tid * 8 + e];
            int   ic  = mi1[tid * 8 + e];
            if (v1c > V1 || (v1c == V1 && ic < I1)) {
                V2 = fmaxf(V1, v2c);
                V1 = v1c;
                I1 = ic;
            } else {
                V2 = fmaxf(V2, v1c);   // v2c <= v1c, so v1c is the only new V2 candidate
            }
        }
        int gi = b * NPTS + row0 + tid;
        g_v1[gi] = V1;
        g_v2[gi] = V2;
        g_i1[gi] = I1;
    }
}

// ---------------------------------------------------------------------------
// Kernel 2: per-batch stable two-bucket compaction (unchanged, ~7us).
// ---------------------------------------------------------------------------
__global__ __launch_bounds__(1024) void compact_kernel(int* __restrict__ out) {
    const int b    = blockIdx.x;
    const int tid  = threadIdx.x;
    const int base = b * NPTS;

    bool m[4];
    int  d[4];
    int  cl = 0;
#pragma unroll
    for (int j = 0; j < 4; j++) {
        int g = tid * 4 + j;
        float v1 = g_v1[base + g];
        float v2 = g_v2[base + g];
        m[j] = (v1 / (v2 + EPSV)) < RATIO;
        d[j] = g_i1[base + g];
        cl += m[j];
    }

    const int lane = tid & 31;
    const int warp = tid >> 5;
    int inc = cl;
#pragma unroll
    for (int o = 1; o < 32; o <<= 1) {
        int y = __shfl_up_sync(0xffffffffu, inc, o);
        if (lane >= o) inc += y;
    }

    __shared__ int wsum[32];
    __shared__ int woff[32];
    __shared__ int totalS;
    if (lane == 31) wsum[warp] = inc;
    __syncthreads();
    if (tid == 0) {
        int acc = 0;
        for (int w = 0; w < 32; w++) { woff[w] = acc; acc += wsum[w]; }
        totalS = acc;
    }
    __syncthreads();

    const int cnt = totalS;
    int vb = woff[warp] + (inc - cl);

    int2* o2 = (int2*)out + b * NPTS;
#pragma unroll
    for (int j = 0; j < 4; j++) {
        int g = tid * 4 + j;
        int  pos;
        int2 val;
        if (m[j]) { pos = vb; val = make_int2(g, d[j]); vb++; }
        else      { pos = cnt + (g - vb); val = make_int2(0, 0); }
        o2[pos] = val;
    }
}

extern "C" void kernel_launch(void* const* d_in, const int* in_sizes, int n_in,
                              void* d_out, int out_size) {
    const float* d1 = (const float*)d_in[0];
    const float* d2 = (const float*)d_in[1];
    (void)in_sizes; (void)n_in; (void)out_size;

    cudaFuncSetAttribute(sim_top2_mma, cudaFuncAttributeMaxDynamicSharedMemorySize,
                         SM_FLOATS * (int)sizeof(float));

    dim3 grid(NPTS / TM, BATCH);
    sim_top2_mma<<<grid, 256, SM_FLOATS * sizeof(float)>>>(d1, d2);
    compact_kernel<<<BATCH, 1024>>>((int*)d_out);
}

// round 14
// speedup vs baseline: 1.1312x; 1.1312x over previous
#include <cuda_runtime.h>
#include <cstdint>

#define BATCH 4
#define NPTS  4096
#define DIM   128
#define TM    128          // desc1 rows per CTA
#define TN    64           // desc2 rows per col-tile
#define NTILES (NPTS / TN) // 64
#define SSTR  136          // smem row stride in floats (DIM + 8): 136 % 32 == 8 -> conflict-free LDS.64
#define RATIO 0.85f
#define EPSV  1e-8f

// Scratch (allocation-free rule: __device__ globals)
__device__ float g_v1[BATCH * NPTS];
__device__ float g_v2[BATCH * NPTS];
__device__ int   g_i1[BATCH * NPTS];

// dynamic smem layout in floats
#define A_HI 0
#define A_LO (TM * SSTR)
#define B_HI (2 * TM * SSTR)
#define B_LO (2 * TM * SSTR + TN * SSTR)
#define SM_FLOATS (2 * TM * SSTR + 2 * TN * SSTR)   // 52224 floats = 208896 B

__device__ __forceinline__ uint32_t f2tf32(float x) {
    uint32_t r;
    asm("cvt.rna.tf32.f32 %0, %1;" : "=r"(r) : "f"(x));
    return r;
}

__device__ __forceinline__ void mma_tf32(float* c, const uint32_t* a, uint32_t b0, uint32_t b1) {
    asm volatile(
        "mma.sync.aligned.m16n8k8.row.col.f32.tf32.tf32.f32 "
        "{%0,%1,%2,%3}, {%4,%5,%6,%7}, {%8,%9}, {%0,%1,%2,%3};"
        : "+f"(c[0]), "+f"(c[1]), "+f"(c[2]), "+f"(c[3])
        : "r"(a[0]), "r"(a[1]), "r"(a[2]), "r"(a[3]), "r"(b0), "r"(b1));
}

// Split 8 logical k-values (two float4) into tf32 hi/lo and store k-interleaved:
// physical order k0,k4,k1,k5,k2,k6,k3,k7 so fragment pairs (k, k+4) are 8B-adjacent.
__device__ __forceinline__ void split8_store(float* hi_p, float* lo_p, float4 v0, float4 v1) {
    float p0 = v0.x, p1 = v1.x, p2 = v0.y, p3 = v1.y;
    float p4 = v0.z, p5 = v1.z, p6 = v0.w, p7 = v1.w;
    uint4 h0, h1, l0, l1;
    h0.x = f2tf32(p0); h0.y = f2tf32(p1); h0.z = f2tf32(p2); h0.w = f2tf32(p3);
    h1.x = f2tf32(p4); h1.y = f2tf32(p5); h1.z = f2tf32(p6); h1.w = f2tf32(p7);
    l0.x = f2tf32(p0 - __uint_as_float(h0.x));
    l0.y = f2tf32(p1 - __uint_as_float(h0.y));
    l0.z = f2tf32(p2 - __uint_as_float(h0.z));
    l0.w = f2tf32(p3 - __uint_as_float(h0.w));
    l1.x = f2tf32(p4 - __uint_as_float(h1.x));
    l1.y = f2tf32(p5 - __uint_as_float(h1.y));
    l1.z = f2tf32(p6 - __uint_as_float(h1.z));
    l1.w = f2tf32(p7 - __uint_as_float(h1.w));
    *(uint4*)hi_p       = h0;
    *(uint4*)(hi_p + 4) = h1;
    *(uint4*)lo_p       = l0;
    *(uint4*)(lo_p + 4) = l1;
}

// ---------------------------------------------------------------------------
// Kernel 1: 3xTF32 mma.sync GEMM (sim = D1 * D2^T) with fused per-row top-2.
// 256 threads = 8 warps (4 m x 2 n), warp tile 32x32. Conflict-free LDS.64
// fragment loads (SSTR=136 + k-interleave); register-prefetched B tiles.
// ---------------------------------------------------------------------------
__global__ __launch_bounds__(256, 1) void sim_top2_mma(const float* __restrict__ d1,
                                                       const float* __restrict__ d2) {
    extern __shared__ float sm[];

    const int tid  = threadIdx.x;
    const int wid  = tid >> 5;
    const int lane = tid & 31;
    const int g    = lane >> 2;     // fragment row group
    const int tig  = lane & 3;      // thread in group
    const int wm   = wid & 3;       // warp m-group: rows wm*32..+31
    const int wn   = wid >> 2;      // warp n-group: cols wn*32..+31

    const int b    = blockIdx.y;
    const int row0 = blockIdx.x * TM;

    // ---- load + split A tile [TM x DIM], k-interleaved (once) ----
    {
        const float4* A = (const float4*)(d1 + (size_t)b * NPTS * DIM);
#pragma unroll
        for (int c = 0; c < 8; c++) {
            int i   = tid + 256 * c;          // chunk id: TM*DIM/8 = 2048 chunks
            int row = i >> 4, k8 = i & 15;
            float4 v0 = A[(size_t)(row0 + row) * 32 + 2 * k8];
            float4 v1 = A[(size_t)(row0 + row) * 32 + 2 * k8 + 1];
            split8_store(sm + A_HI + row * SSTR + k8 * 8,
                         sm + A_LO + row * SSTR + k8 * 8, v0, v1);
        }
    }

    // warp-local smem bases
    const float* As_hi = sm + A_HI + (wm * 32) * SSTR;
    const float* As_lo = sm + A_LO + (wm * 32) * SSTR;
    const float* Bs_hi = sm + B_HI + (wn * 32) * SSTR;
    const float* Bs_lo = sm + B_LO + (wn * 32) * SSTR;

    float t1[4], t2[4];
    int   i1[4];
#pragma unroll
    for (int s = 0; s < 4; s++) { t1[s] = -1e30f; t2[s] = -1e30f; i1[s] = 0; }

    const float4* Bm = (const float4*)(d2 + (size_t)b * NPTS * DIM);

    // prefetch tile 0 into registers (4 chunks x 2 float4 per thread)
    float4 pre[8];
#pragma unroll
    for (int c = 0; c < 4; c++) {
        int i   = tid + 256 * c;              // TN*DIM/8 = 1024 chunks
        int row = i >> 4, k8 = i & 15;
        pre[2 * c]     = Bm[(size_t)row * 32 + 2 * k8];
        pre[2 * c + 1] = Bm[(size_t)row * 32 + 2 * k8 + 1];
    }

    for (int t = 0; t < NTILES; t++) {
        const int c0 = t * TN;

        __syncthreads();  // tile t-1 readers done (t=0: covers A stores too)
#pragma unroll
        for (int c = 0; c < 4; c++) {
            int i   = tid + 256 * c;
            int row = i >> 4, k8 = i & 15;
            split8_store(sm + B_HI + row * SSTR + k8 * 8,
                         sm + B_LO + row * SSTR + k8 * 8, pre[2 * c], pre[2 * c + 1]);
        }
        __syncthreads();

        // prefetch tile t+1 (hidden behind the HMMA loop below)
        if (t + 1 < NTILES) {
            const float4* Bn = Bm + (size_t)(c0 + TN) * 32;
#pragma unroll
            for (int c = 0; c < 4; c++) {
                int i   = tid + 256 * c;
                int row = i >> 4, k8 = i & 15;
                pre[2 * c]     = Bn[(size_t)row * 32 + 2 * k8];
                pre[2 * c + 1] = Bn[(size_t)row * 32 + 2 * k8 + 1];
            }
        }

        float acc[2][4][4];
#pragma unroll
        for (int mt = 0; mt < 2; mt++)
#pragma unroll
            for (int nt = 0; nt < 4; nt++)
#pragma unroll
                for (int c = 0; c < 4; c++) acc[mt][nt][c] = 0.f;

#pragma unroll 8
        for (int ks = 0; ks < 16; ks++) {
            const int kb = ks * 8 + 2 * tig;

            // B fragments: one LDS.64 -> (b0, b1) = (k0+tig, k0+tig+4)
            uint2 bh[4], bl[4];
#pragma unroll
            for (int nt = 0; nt < 4; nt++) {
                int off = (nt * 8 + g) * SSTR + kb;
                bh[nt] = *(const uint2*)(Bs_hi + off);
                bl[nt] = *(const uint2*)(Bs_lo + off);
            }

#pragma unroll
            for (int mt = 0; mt < 2; mt++) {
                int off = (mt * 16 + g) * SSTR + kb;
                uint2 a02h = *(const uint2*)(As_hi + off);
                uint2 a13h = *(const uint2*)(As_hi + off + 8 * SSTR);
                uint2 a02l = *(const uint2*)(As_lo + off);
                uint2 a13l = *(const uint2*)(As_lo + off + 8 * SSTR);
                uint32_t ah[4] = {a02h.x, a13h.x, a02h.y, a13h.y};
                uint32_t al[4] = {a02l.x, a13l.x, a02l.y, a13l.y};
#pragma unroll
                for (int nt = 0; nt < 4; nt++) {
                    mma_tf32(acc[mt][nt], ah, bh[nt].x, bh[nt].y);  // hi*hi
                    mma_tf32(acc[mt][nt], ah, bl[nt].x, bl[nt].y);  // hi*lo
                    mma_tf32(acc[mt][nt], al, bh[nt].x, bh[nt].y);  // lo*hi
                }
            }
        }

        // Fused running top-2: slot s = mt*2 + h owns row (mt*16 + h*8 + g).
        // Columns ascend -> strict '>' keeps lowest index on ties (top_k semantics).
#pragma unroll
        for (int mt = 0; mt < 2; mt++) {
#pragma unroll
            for (int h = 0; h < 2; h++) {
                const int s = mt * 2 + h;
#pragma unroll
                for (int nt = 0; nt < 4; nt++) {
#pragma unroll
                    for (int j = 0; j < 2; j++) {
                        float v = acc[mt][nt][h * 2 + j];
                        int   c = c0 + wn * 32 + nt * 8 + 2 * tig + j;
                        if (v > t1[s])      { t2[s] = t1[s]; t1[s] = v; i1[s] = c; }
                        else if (v > t2[s]) { t2[s] = v; }
                    }
                }
            }
        }
    }

    // ---- final merge: 8 partials per row (2 warp_n x 4 tig), reuse smem ----
    __syncthreads();
    float* mv1 = sm;                  // [128][8]
    float* mv2 = sm + 1024;
    int*   mi1 = (int*)(sm + 2048);

#pragma unroll
    for (int s = 0; s < 4; s++) {
        int r = wm * 32 + s * 8 + g;
        int e = wn * 4 + tig;
        mv1[r * 8 + e] = t1[s];
        mv2[r * 8 + e] = t2[s];
        mi1[r * 8 + e] = i1[s];
    }
    __syncthreads();

    if (tid < TM) {
        float V1 = -1e30f, V2 = -1e30f;
        int   I1 = 0;
#pragma unroll
        for (int e = 0; e < 8; e++) {
            float v1c = mv1[tid * 8 + e];
            float v2c = mv2[tid * 8 + e];
            int   ic  = mi1[tid * 8 + e];
            if (v1c > V1 || (v1c == V1 && ic < I1)) {
                V2 = fmaxf(V1, v2c);
                V1 = v1c;
                I1 = ic;
            } else {
                V2 = fmaxf(V2, v1c);   // v2c <= v1c, so v1c is the only new V2 candidate
            }
        }
        int gi = b * NPTS + row0 + tid;
        g_v1[gi] = V1;
        g_v2[gi] = V2;
        g_i1[gi] = I1;
    }
}

// ---------------------------------------------------------------------------
// Kernel 2: per-batch stable two-bucket compaction (unchanged, ~7us).
// ---------------------------------------------------------------------------
__global__ __launch_bounds__(1024) void compact_kernel(int* __restrict__ out) {
    const int b    = blockIdx.x;
    const int tid  = threadIdx.x;
    const int base = b * NPTS;

    bool m[4];
    int  d[4];
    int  cl = 0;
#pragma unroll
    for (int j = 0; j < 4; j++) {
        int g = tid * 4 + j;
        float v1 = g_v1[base + g];
        float v2 = g_v2[base + g];
        m[j] = (v1 / (v2 + EPSV)) < RATIO;
        d[j] = g_i1[base + g];
        cl += m[j];
    }

    const int lane = tid & 31;
    const int warp = tid >> 5;
    int inc = cl;
#pragma unroll
    for (int o = 1; o < 32; o <<= 1) {
        int y = __shfl_up_sync(0xffffffffu, inc, o);
        if (lane >= o) inc += y;
    }

    __shared__ int wsum[32];
    __shared__ int woff[32];
    __shared__ int totalS;
    if (lane == 31) wsum[warp] = inc;
    __syncthreads();
    if (tid == 0) {
        int acc = 0;
        for (int w = 0; w < 32; w++) { woff[w] = acc; acc += wsum[w]; }
        totalS = acc;
    }
    __syncthreads();

    const int cnt = totalS;
    int vb = woff[warp] + (inc - cl);

    int2* o2 = (int2*)out + b * NPTS;
#pragma unroll
    for (int j = 0; j < 4; j++) {
        int g = tid * 4 + j;
        int  pos;
        int2 val;
        if (m[j]) { pos = vb; val = make_int2(g, d[j]); vb++; }
        else      { pos = cnt + (g - vb); val = make_int2(0, 0); }
        o2[pos] = val;
    }
}

extern "C" void kernel_launch(void* const* d_in, const int* in_sizes, int n_in,
                              void* d_out, int out_size) {
    const float* d1 = (const float*)d_in[0];
    const float* d2 = (const float*)d_in[1];
    (void)in_sizes; (void)n_in; (void)out_size;

    cudaFuncSetAttribute(sim_top2_mma, cudaFuncAttributeMaxDynamicSharedMemorySize,
                         SM_FLOATS * (int)sizeof(float));

    dim3 grid(NPTS / TM, BATCH);
    sim_top2_mma<<<grid, 256, SM_FLOATS * sizeof(float)>>>(d1, d2);
    compact_kernel<<<BATCH, 1024>>>((int*)d_out);
}

// round 15
// speedup vs baseline: 1.1443x; 1.0116x over previous
#include <cuda_runtime.h>
#include <cstdint>

#define BATCH 4
#define NPTS  4096
#define DIM   128
#define TM    128          // desc1 rows per CTA
#define TN    64           // desc2 rows per col-tile
#define NTILES (NPTS / TN) // 64
#define SSTR  136          // smem row stride in floats (DIM + 8): 136 % 32 == 8 -> conflict-free LDS.64
#define RATIO 0.85f
#define EPSV  1e-8f

// Scratch (allocation-free rule: __device__ globals)
__device__ float g_v1[BATCH * NPTS];
__device__ float g_v2[BATCH * NPTS];
__device__ int   g_i1[BATCH * NPTS];

// dynamic smem layout in floats
#define A_HI 0
#define A_LO (TM * SSTR)
#define B_HI (2 * TM * SSTR)
#define B_LO (2 * TM * SSTR + TN * SSTR)
#define SM_FLOATS (2 * TM * SSTR + 2 * TN * SSTR)   // 52224 floats = 208896 B

__device__ __forceinline__ uint32_t f2tf32(float x) {
    uint32_t r;
    asm("cvt.rna.tf32.f32 %0, %1;" : "=r"(r) : "f"(x));
    return r;
}

__device__ __forceinline__ void mma_tf32(float* c, const uint32_t* a, uint32_t b0, uint32_t b1) {
    asm volatile(
        "mma.sync.aligned.m16n8k8.row.col.f32.tf32.tf32.f32 "
        "{%0,%1,%2,%3}, {%4,%5,%6,%7}, {%8,%9}, {%0,%1,%2,%3};"
        : "+f"(c[0]), "+f"(c[1]), "+f"(c[2]), "+f"(c[3])
        : "r"(a[0]), "r"(a[1]), "r"(a[2]), "r"(a[3]), "r"(b0), "r"(b1));
}

// Split 8 logical k-values (two float4) into tf32 hi/lo and store k-interleaved:
// physical order k0,k4,k1,k5,k2,k6,k3,k7 so fragment pairs (k, k+4) are 8B-adjacent.
__device__ __forceinline__ void split8_store(float* hi_p, float* lo_p, float4 v0, float4 v1) {
    float p0 = v0.x, p1 = v1.x, p2 = v0.y, p3 = v1.y;
    float p4 = v0.z, p5 = v1.z, p6 = v0.w, p7 = v1.w;
    uint4 h0, h1, l0, l1;
    h0.x = f2tf32(p0); h0.y = f2tf32(p1); h0.z = f2tf32(p2); h0.w = f2tf32(p3);
    h1.x = f2tf32(p4); h1.y = f2tf32(p5); h1.z = f2tf32(p6); h1.w = f2tf32(p7);
    l0.x = f2tf32(p0 - __uint_as_float(h0.x));
    l0.y = f2tf32(p1 - __uint_as_float(h0.y));
    l0.z = f2tf32(p2 - __uint_as_float(h0.z));
    l0.w = f2tf32(p3 - __uint_as_float(h0.w));
    l1.x = f2tf32(p4 - __uint_as_float(h1.x));
    l1.y = f2tf32(p5 - __uint_as_float(h1.y));
    l1.z = f2tf32(p6 - __uint_as_float(h1.z));
    l1.w = f2tf32(p7 - __uint_as_float(h1.w));
    *(uint4*)hi_p       = h0;
    *(uint4*)(hi_p + 4) = h1;
    *(uint4*)lo_p       = l0;
    *(uint4*)(lo_p + 4) = l1;
}

// ---------------------------------------------------------------------------
// Kernel 1: 3xTF32 mma.sync GEMM (sim = D1 * D2^T) with fused per-row top-2.
// 256 threads = 8 warps (4 m x 2 n), warp tile 32x32. Conflict-free LDS.64
// fragment loads (SSTR=136 + k-interleave). No register prefetch: those 32
// registers go to ptxas for LDS->HMMA software pipelining instead.
// ---------------------------------------------------------------------------
__global__ __launch_bounds__(256, 1) void sim_top2_mma(const float* __restrict__ d1,
                                                       const float* __restrict__ d2) {
    extern __shared__ float sm[];

    const int tid  = threadIdx.x;
    const int wid  = tid >> 5;
    const int lane = tid & 31;
    const int g    = lane >> 2;     // fragment row group
    const int tig  = lane & 3;      // thread in group
    const int wm   = wid & 3;       // warp m-group: rows wm*32..+31
    const int wn   = wid >> 2;      // warp n-group: cols wn*32..+31

    const int b    = blockIdx.y;
    const int row0 = blockIdx.x * TM;

    // ---- load + split A tile [TM x DIM], k-interleaved (once) ----
    {
        const float4* A = (const float4*)(d1 + (size_t)b * NPTS * DIM);
#pragma unroll
        for (int c = 0; c < 8; c++) {
            int i   = tid + 256 * c;          // chunk id: TM*DIM/8 = 2048 chunks
            int row = i >> 4, k8 = i & 15;
            float4 v0 = A[(size_t)(row0 + row) * 32 + 2 * k8];
            float4 v1 = A[(size_t)(row0 + row) * 32 + 2 * k8 + 1];
            split8_store(sm + A_HI + row * SSTR + k8 * 8,
                         sm + A_LO + row * SSTR + k8 * 8, v0, v1);
        }
    }

    // warp-local smem bases
    const float* As_hi = sm + A_HI + (wm * 32) * SSTR;
    const float* As_lo = sm + A_LO + (wm * 32) * SSTR;
    const float* Bs_hi = sm + B_HI + (wn * 32) * SSTR;
    const float* Bs_lo = sm + B_LO + (wn * 32) * SSTR;

    float t1[4], t2[4];
    int   i1[4];
#pragma unroll
    for (int s = 0; s < 4; s++) { t1[s] = -1e30f; t2[s] = -1e30f; i1[s] = 0; }

    const float4* Bm = (const float4*)(d2 + (size_t)b * NPTS * DIM);

    for (int t = 0; t < NTILES; t++) {
        const int c0 = t * TN;

        __syncthreads();  // tile t-1 readers done (t=0: covers A stores too)
#pragma unroll
        for (int c = 0; c < 4; c++) {
            int i   = tid + 256 * c;          // TN*DIM/8 = 1024 chunks
            int row = i >> 4, k8 = i & 15;
            float4 v0 = Bm[(size_t)(c0 + row) * 32 + 2 * k8];
            float4 v1 = Bm[(size_t)(c0 + row) * 32 + 2 * k8 + 1];
            split8_store(sm + B_HI + row * SSTR + k8 * 8,
                         sm + B_LO + row * SSTR + k8 * 8, v0, v1);
        }
        __syncthreads();

        float acc[2][4][4];
#pragma unroll
        for (int mt = 0; mt < 2; mt++)
#pragma unroll
            for (int nt = 0; nt < 4; nt++)
#pragma unroll
                for (int c = 0; c < 4; c++) acc[mt][nt][c] = 0.f;

#pragma unroll 8
        for (int ks = 0; ks < 16; ks++) {
            const int kb = ks * 8 + 2 * tig;

            // B fragments: one LDS.64 -> (b0, b1) = (k0+tig, k0+tig+4)
            uint2 bh[4], bl[4];
#pragma unroll
            for (int nt = 0; nt < 4; nt++) {
                int off = (nt * 8 + g) * SSTR + kb;
                bh[nt] = *(const uint2*)(Bs_hi + off);
                bl[nt] = *(const uint2*)(Bs_lo + off);
            }

#pragma unroll
            for (int mt = 0; mt < 2; mt++) {
                int off = (mt * 16 + g) * SSTR + kb;
                uint2 a02h = *(const uint2*)(As_hi + off);
                uint2 a13h = *(const uint2*)(As_hi + off + 8 * SSTR);
                uint2 a02l = *(const uint2*)(As_lo + off);
                uint2 a13l = *(const uint2*)(As_lo + off + 8 * SSTR);
                uint32_t ah[4] = {a02h.x, a13h.x, a02h.y, a13h.y};
                uint32_t al[4] = {a02l.x, a13l.x, a02l.y, a13l.y};
#pragma unroll
                for (int nt = 0; nt < 4; nt++) {
                    mma_tf32(acc[mt][nt], ah, bh[nt].x, bh[nt].y);  // hi*hi
                    mma_tf32(acc[mt][nt], ah, bl[nt].x, bl[nt].y);  // hi*lo
                    mma_tf32(acc[mt][nt], al, bh[nt].x, bh[nt].y);  // lo*hi
                }
            }
        }

        // Fused running top-2: slot s = mt*2 + h owns row (mt*16 + h*8 + g).
        // Columns ascend -> strict '>' keeps lowest index on ties (top_k semantics).
#pragma unroll
        for (int mt = 0; mt < 2; mt++) {
#pragma unroll
            for (int h = 0; h < 2; h++) {
                const int s = mt * 2 + h;
#pragma unroll
                for (int nt = 0; nt < 4; nt++) {
#pragma unroll
                    for (int j = 0; j < 2; j++) {
                        float v = acc[mt][nt][h * 2 + j];
                        int   c = c0 + wn * 32 + nt * 8 + 2 * tig + j;
                        if (v > t1[s])      { t2[s] = t1[s]; t1[s] = v; i1[s] = c; }
                        else if (v > t2[s]) { t2[s] = v; }
                    }
                }
            }
        }
    }

    // ---- final merge: 8 partials per row (2 warp_n x 4 tig), reuse smem ----
    __syncthreads();
    float* mv1 = sm;                  // [128][8]
    float* mv2 = sm + 1024;
    int*   mi1 = (int*)(sm + 2048);

#pragma unroll
    for (int s = 0; s < 4; s++) {
        int r = wm * 32 + s * 8 + g;
        int e = wn * 4 + tig;
        mv1[r * 8 + e] = t1[s];
        mv2[r * 8 + e] = t2[s];
        mi1[r * 8 + e] = i1[s];
    }
    __syncthreads();

    if (tid < TM) {
        float V1 = -1e30f, V2 = -1e30f;
        int   I1 = 0;
#pragma unroll
        for (int e = 0; e < 8; e++) {
            float v1c = mv1[tid * 8 + e];
            float v2c = mv2[tid * 8 + e];
            int   ic  = mi1[tid * 8 + e];
            if (v1c > V1 || (v1c == V1 && ic < I1)) {
                V2 = fmaxf(V1, v2c);
                V1 = v1c;
                I1 = ic;
            } else {
                V2 = fmaxf(V2, v1c);   // v2c <= v1c, so v1c is the only new V2 candidate
            }
        }
        int gi = b * NPTS + row0 + tid;
        g_v1[gi] = V1;
        g_v2[gi] = V2;
        g_i1[gi] = I1;
    }
}

// ---------------------------------------------------------------------------
// Kernel 2: per-batch stable two-bucket compaction (unchanged, ~7us).
// ---------------------------------------------------------------------------
__global__ __launch_bounds__(1024) void compact_kernel(int* __restrict__ out) {
    const int b    = blockIdx.x;
    const int tid  = threadIdx.x;
    const int base = b * NPTS;

    bool m[4];
    int  d[4];
    int  cl = 0;
#pragma unroll
    for (int j = 0; j < 4; j++) {
        int g = tid * 4 + j;
        float v1 = g_v1[base + g];
        float v2 = g_v2[base + g];
        m[j] = (v1 / (v2 + EPSV)) < RATIO;
        d[j] = g_i1[base + g];
        cl += m[j];
    }

    const int lane = tid & 31;
    const int warp = tid >> 5;
    int inc = cl;
#pragma unroll
    for (int o = 1; o < 32; o <<= 1) {
        int y = __shfl_up_sync(0xffffffffu, inc, o);
        if (lane >= o) inc += y;
    }

    __shared__ int wsum[32];
    __shared__ int woff[32];
    __shared__ int totalS;
    if (lane == 31) wsum[warp] = inc;
    __syncthreads();
    if (tid == 0) {
        int acc = 0;
        for (int w = 0; w < 32; w++) { woff[w] = acc; acc += wsum[w]; }
        totalS = acc;
    }
    __syncthreads();

    const int cnt = totalS;
    int vb = woff[warp] + (inc - cl);

    int2* o2 = (int2*)out + b * NPTS;
#pragma unroll
    for (int j = 0; j < 4; j++) {
        int g = tid * 4 + j;
        int  pos;
        int2 val;
        if (m[j]) { pos = vb; val = make_int2(g, d[j]); vb++; }
        else      { pos = cnt + (g - vb); val = make_int2(0, 0); }
        o2[pos] = val;
    }
}

extern "C" void kernel_launch(void* const* d_in, const int* in_sizes, int n_in,
                              void* d_out, int out_size) {
    const float* d1 = (const float*)d_in[0];
    const float* d2 = (const float*)d_in[1];
    (void)in_sizes; (void)n_in; (void)out_size;

    cudaFuncSetAttribute(sim_top2_mma, cudaFuncAttributeMaxDynamicSharedMemorySize,
                         SM_FLOATS * (int)sizeof(float));

    dim3 grid(NPTS / TM, BATCH);
    sim_top2_mma<<<grid, 256, SM_FLOATS * sizeof(float)>>>(d1, d2);
    compact_kernel<<<BATCH, 1024>>>((int*)d_out);
}

// round 17
// speedup vs baseline: 1.2060x; 1.0539x over previous
#include <cuda_runtime.h>
#include <cstdint>

#define BATCH 4
#define NPTS  4096
#define DIM   128
#define TM    128          // desc1 rows per CTA
#define TN    64           // desc2 rows per col-tile
#define NTILES (NPTS / TN) // 64
#define SSTR  132          // smem row stride in floats (DIM + 4 pad) -> conflict-free scalar frags
#define RATIO 0.85f
#define EPSV  1e-8f

// Scratch (allocation-free rule: __device__ globals)
__device__ float g_v1[BATCH * NPTS];
__device__ float g_v2[BATCH * NPTS];
__device__ int   g_i1[BATCH * NPTS];

// dynamic smem layout in floats
#define A_HI 0
#define A_LO (TM * SSTR)
#define B_HI (2 * TM * SSTR)
#define B_LO (2 * TM * SSTR + TN * SSTR)
#define SM_FLOATS (2 * TM * SSTR + 2 * TN * SSTR)   // 50688 floats = 202752 B

__device__ __forceinline__ uint32_t f2tf32(float x) {
    uint32_t r;
    asm("cvt.rna.tf32.f32 %0, %1;" : "=r"(r) : "f"(x));
    return r;
}

__device__ __forceinline__ void mma_tf32(float* c, const uint32_t* a, const uint32_t* b) {
    asm volatile(
        "mma.sync.aligned.m16n8k8.row.col.f32.tf32.tf32.f32 "
        "{%0,%1,%2,%3}, {%4,%5,%6,%7}, {%8,%9}, {%0,%1,%2,%3};"
        : "+f"(c[0]), "+f"(c[1]), "+f"(c[2]), "+f"(c[3])
        : "r"(a[0]), "r"(a[1]), "r"(a[2]), "r"(a[3]), "r"(b[0]), "r"(b[1]));
}

// Split a float4 into tf32 hi/lo and store both as float4 into smem (R6 layout).
__device__ __forceinline__ void split_store(float* hi_p, float* lo_p, float4 v) {
    uint4 h, l;
    h.x = f2tf32(v.x); h.y = f2tf32(v.y); h.z = f2tf32(v.z); h.w = f2tf32(v.w);
    l.x = f2tf32(v.x - __uint_as_float(h.x));
    l.y = f2tf32(v.y - __uint_as_float(h.y));
    l.z = f2tf32(v.z - __uint_as_float(h.z));
    l.w = f2tf32(v.w - __uint_as_float(h.w));
    *(uint4*)hi_p = h;
    *(uint4*)lo_p = l;
}

// ---------------------------------------------------------------------------
// Kernel 1: 3xTF32 mma.sync GEMM (sim = D1 * D2^T) with fused per-row top-2.
// 256 threads = 8 warps (4 m x 2 n), warp tile 32x32. R6 memory layout.
// PASS-MAJOR MMA ordering: all hi*hi, then all hi*lo, then all lo*hi, so
// same-accumulator HMMAs are 8 apart instead of back-to-back (kills the
// 3-deep dependent-HMMA chains that were stalling the tensor pipe).
// ---------------------------------------------------------------------------
__global__ __launch_bounds__(256, 1) void sim_top2_mma(const float* __restrict__ d1,
                                                       const float* __restrict__ d2) {
    extern __shared__ float sm[];

    const int tid  = threadIdx.x;
    const int wid  = tid >> 5;
    const int lane = tid & 31;
    const int g    = lane >> 2;     // fragment row group
    const int tig  = lane & 3;      // thread in group
    const int wm   = wid & 3;       // warp m-group: rows wm*32..+31
    const int wn   = wid >> 2;      // warp n-group: cols wn*32..+31

    const int b    = blockIdx.y;
    const int row0 = blockIdx.x * TM;

    // ---- load + split A tile [TM x DIM] (once) ----
    {
        const float4* A = (const float4*)(d1 + (size_t)b * NPTS * DIM);
        for (int i = tid; i < (DIM / 4) * TM; i += 256) {
            int row = i >> 5, k4 = i & 31;
            float4 v = A[(size_t)(row0 + row) * (DIM / 4) + k4];
            split_store(sm + A_HI + row * SSTR + 4 * k4,
                        sm + A_LO + row * SSTR + 4 * k4, v);
        }
    }

    // warp-local smem bases
    const float* As_hi = sm + A_HI + (wm * 32) * SSTR;
    const float* As_lo = sm + A_LO + (wm * 32) * SSTR;
    const float* Bs_hi = sm + B_HI + (wn * 32) * SSTR;
    const float* Bs_lo = sm + B_LO + (wn * 32) * SSTR;

    float t1[4], t2[4];
    int   i1[4];
#pragma unroll
    for (int s = 0; s < 4; s++) { t1[s] = -1e30f; t2[s] = -1e30f; i1[s] = 0; }

    const float4* Bm = (const float4*)(d2 + (size_t)b * NPTS * DIM);

    for (int t = 0; t < NTILES; t++) {
        const int c0 = t * TN;

        __syncthreads();  // tile t-1 readers done (t=0: covers A stores too)
        for (int i = tid; i < (DIM / 4) * TN; i += 256) {
            int row = i >> 5, k4 = i & 31;
            float4 v = Bm[(size_t)(c0 + row) * (DIM / 4) + k4];
            split_store(sm + B_HI + row * SSTR + 4 * k4,
                        sm + B_LO + row * SSTR + 4 * k4, v);
        }
        __syncthreads();

        float acc[2][4][4];
#pragma unroll
        for (int mt = 0; mt < 2; mt++)
#pragma unroll
            for (int nt = 0; nt < 4; nt++)
#pragma unroll
                for (int c = 0; c < 4; c++) acc[mt][nt][c] = 0.f;

#pragma unroll 16
        for (int ks = 0; ks < 16; ks++) {
            const int kb = ks * 8 + tig;

            // --- load all fragments for this K-step (scalar, conflict-free) ---
            uint32_t bh[4][2], bl[4][2];
#pragma unroll
            for (int nt = 0; nt < 4; nt++) {
                int off = (nt * 8 + g) * SSTR + kb;
                bh[nt][0] = __float_as_uint(Bs_hi[off]);
                bh[nt][1] = __float_as_uint(Bs_hi[off + 4]);
                bl[nt][0] = __float_as_uint(Bs_lo[off]);
                bl[nt][1] = __float_as_uint(Bs_lo[off + 4]);
            }
            uint32_t ah[2][4], al[2][4];
#pragma unroll
            for (int mt = 0; mt < 2; mt++) {
                int off = (mt * 16 + g) * SSTR + kb;
                ah[mt][0] = __float_as_uint(As_hi[off]);
                ah[mt][1] = __float_as_uint(As_hi[off + 8 * SSTR]);
                ah[mt][2] = __float_as_uint(As_hi[off + 4]);
                ah[mt][3] = __float_as_uint(As_hi[off + 8 * SSTR + 4]);
                al[mt][0] = __float_as_uint(As_lo[off]);
                al[mt][1] = __float_as_uint(As_lo[off + 8 * SSTR]);
                al[mt][2] = __float_as_uint(As_lo[off + 4]);
                al[mt][3] = __float_as_uint(As_lo[off + 8 * SSTR + 4]);
            }

            // --- pass-major MMA order: same-acc reuse distance = 8 MMAs ---
#pragma unroll
            for (int mt = 0; mt < 2; mt++)
#pragma unroll
                for (int nt = 0; nt < 4; nt++)
                    mma_tf32(acc[mt][nt], ah[mt], bh[nt]);   // hi*hi
#pragma unroll
            for (int mt = 0; mt < 2; mt++)
#pragma unroll
                for (int nt = 0; nt < 4; nt++)
                    mma_tf32(acc[mt][nt], ah[mt], bl[nt]);   // hi*lo
#pragma unroll
            for (int mt = 0; mt < 2; mt++)
#pragma unroll
                for (int nt = 0; nt < 4; nt++)
                    mma_tf32(acc[mt][nt], al[mt], bh[nt]);   // lo*hi
        }

        // Fused running top-2: slot s = mt*2 + h owns row (mt*16 + h*8 + g).
        // Columns ascend -> strict '>' keeps lowest index on ties (top_k semantics).
#pragma unroll
        for (int mt = 0; mt < 2; mt++) {
#pragma unroll
            for (int h = 0; h < 2; h++) {
                const int s = mt * 2 + h;
#pragma unroll
                for (int nt = 0; nt < 4; nt++) {
#pragma unroll
                    for (int j = 0; j < 2; j++) {
                        float v = acc[mt][nt][h * 2 + j];
                        int   c = c0 + wn * 32 + nt * 8 + 2 * tig + j;
                        if (v > t1[s])      { t2[s] = t1[s]; t1[s] = v; i1[s] = c; }
                        else if (v > t2[s]) { t2[s] = v; }
                    }
                }
            }
        }
    }

    // ---- final merge: 8 partials per row (2 warp_n x 4 tig), reuse smem ----
    __syncthreads();
    float* mv1 = sm;                  // [128][8]
    float* mv2 = sm + 1024;
    int*   mi1 = (int*)(sm + 2048);

#pragma unroll
    for (int s = 0; s < 4; s++) {
        int r = wm * 32 + s * 8 + g;
        int e = wn * 4 + tig;
        mv1[r * 8 + e] = t1[s];
        mv2[r * 8 + e] = t2[s];
        mi1[r * 8 + e] = i1[s];
    }
    __syncthreads();

    if (tid < TM) {
        float V1 = -1e30f, V2 = -1e30f;
        int   I1 = 0;
#pragma unroll
        for (int e = 0; e < 8; e++) {
            float v1c = mv1[tid * 8 + e];
            float v2c = mv2[tid * 8 + e];
            int   ic  = mi1[tid * 8 + e];
            if (v1c > V1 || (v1c == V1 && ic < I1)) {
                V2 = fmaxf(V1, v2c);
                V1 = v1c;
                I1 = ic;
            } else {
                V2 = fmaxf(V2, v1c);   // v2c <= v1c, so v1c is the only new V2 candidate
            }
        }
        int gi = b * NPTS + row0 + tid;
        g_v1[gi] = V1;
        g_v2[gi] = V2;
        g_i1[gi] = I1;
    }
}

// ---------------------------------------------------------------------------
// Kernel 2: per-batch stable two-bucket compaction (unchanged, ~7us).
// ---------------------------------------------------------------------------
__global__ __launch_bounds__(1024) void compact_kernel(int* __restrict__ out) {
    const int b    = blockIdx.x;
    const int tid  = threadIdx.x;
    const int base = b * NPTS;

    bool m[4];
    int  d[4];
    int  cl = 0;
#pragma unroll
    for (int j = 0; j < 4; j++) {
        int g = tid * 4 + j;
        float v1 = g_v1[base + g];
        float v2 = g_v2[base + g];
        m[j] = (v1 / (v2 + EPSV)) < RATIO;
        d[j] = g_i1[base + g];
        cl += m[j];
    }

    const int lane = tid & 31;
    const int warp = tid >> 5;
    int inc = cl;
#pragma unroll
    for (int o = 1; o < 32; o <<= 1) {
        int y = __shfl_up_sync(0xffffffffu, inc, o);
        if (lane >= o) inc += y;
    }

    __shared__ int wsum[32];
    __shared__ int woff[32];
    __shared__ int totalS;
    if (lane == 31) wsum[warp] = inc;
    __syncthreads();
    if (tid == 0) {
        int acc = 0;
        for (int w = 0; w < 32; w++) { woff[w] = acc; acc += wsum[w]; }
        totalS = acc;
    }
    __syncthreads();

    const int cnt = totalS;
    int vb = woff[warp] + (inc - cl);

    int2* o2 = (int2*)out + b * NPTS;
#pragma unroll
    for (int j = 0; j < 4; j++) {
        int g = tid * 4 + j;
        int  pos;
        int2 val;
        if (m[j]) { pos = vb; val = make_int2(g, d[j]); vb++; }
        else      { pos = cnt + (g - vb); val = make_int2(0, 0); }
        o2[pos] = val;
    }
}

extern "C" void kernel_launch(void* const* d_in, const int* in_sizes, int n_in,
                              void* d_out, int out_size) {
    const float* d1 = (const float*)d_in[0];
    const float* d2 = (const float*)d_in[1];
    (void)in_sizes; (void)n_in; (void)out_size;

    cudaFuncSetAttribute(sim_top2_mma, cudaFuncAttributeMaxDynamicSharedMemorySize,
                         SM_FLOATS * (int)sizeof(float));

    dim3 grid(NPTS / TM, BATCH);
    sim_top2_mma<<<grid, 256, SM_FLOATS * sizeof(float)>>>(d1, d2);
    compact_kernel<<<BATCH, 1024>>>((int*)d_out);
}